// round 9
// baseline (speedup 1.0000x reference)
#include <cuda_runtime.h>

#define BATCH 4096
#define FEAT  512
#define NUMC  10000

#define BLOCK_THREADS 256
#define WARPS_PER_BLOCK (BLOCK_THREADS / 32)        // 8
#define GRID_BLOCKS (BATCH / WARPS_PER_BLOCK)       // 512

#define FIX_SCALE 67108864.0                        // 2^26 (Q.26 fixed point)
#define CNT_SHIFT 53
#define SUM_MASK  ((1ULL << CNT_SHIFT) - 1ULL)

// Scratch (no cudaMalloc allowed). Zero-init; reset by the last block each run.
// bits [0,53)  = Q.26 fixed-point sum (max ~2^48; integer adds commutative)
// bits [53,64) = completed-block counter (512 * 2^53 = 2^62 < 2^64)
__device__ unsigned long long g_isum;

// Volatile v4 global load: cannot be sunk/reordered by ptxas -> forces
// front-batched issue (high MLP), which is the whole point of this round.
__device__ __forceinline__ float4 ldg_v4_volatile(const float4* p) {
    float4 v;
    asm volatile("ld.global.nc.v4.f32 {%0,%1,%2,%3}, [%4];"
                 : "=f"(v.x), "=f"(v.y), "=f"(v.z), "=f"(v.w)
                 : "l"(p));
    return v;
}

__global__ void __launch_bounds__(BLOCK_THREADS)
center_loss_kernel(const float* __restrict__ x,
                   const int*   __restrict__ labels32,
                   const float* __restrict__ centers,
                   float*       __restrict__ out) {
    const int lane = threadIdx.x & 31;
    const int wid  = threadIdx.x >> 5;
    const int row  = blockIdx.x * WARPS_PER_BLOCK + wid;

    // dtype probe: odd words of first 64 int32 all zero <=> int64 labels.
    // P(false positive for int32 labels) = 1e-128. Fixed probe, every warp.
    int probe = __ldg(&labels32[2 * lane + 1]);
    int labA  = __ldg(&labels32[2 * row]);    // int64 candidate (low word)
    int labB  = __ldg(&labels32[row]);        // int32 candidate

    // ---- x loads: 4 volatile v4 loads issued BACK-TO-BACK (MLP=4) -----------
    const float4* xr = reinterpret_cast<const float4*>(x + (size_t)row * FEAT);
    float4 xv0 = ldg_v4_volatile(xr + lane);
    float4 xv1 = ldg_v4_volatile(xr + lane + 32);
    float4 xv2 = ldg_v4_volatile(xr + lane + 64);
    float4 xv3 = ldg_v4_volatile(xr + lane + 96);

    bool is64 = (__ballot_sync(0xffffffffu, probe != 0) == 0u);
    int  lab  = is64 ? labA : labB;

    // ---- center loads: 4 volatile v4 loads BACK-TO-BACK (MLP=4) -------------
    const float4* cr = reinterpret_cast<const float4*>(centers + (size_t)lab * FEAT);
    float4 cv0 = ldg_v4_volatile(cr + lane);
    float4 cv1 = ldg_v4_volatile(cr + lane + 32);
    float4 cv2 = ldg_v4_volatile(cr + lane + 64);
    float4 cv3 = ldg_v4_volatile(cr + lane + 96);

    float a0, a1, a2, a3, d;
    d = xv0.x - cv0.x; a0 = d * d;
    d = xv0.y - cv0.y; a1 = d * d;
    d = xv0.z - cv0.z; a2 = d * d;
    d = xv0.w - cv0.w; a3 = d * d;
    d = xv1.x - cv1.x; a0 = fmaf(d, d, a0);
    d = xv1.y - cv1.y; a1 = fmaf(d, d, a1);
    d = xv1.z - cv1.z; a2 = fmaf(d, d, a2);
    d = xv1.w - cv1.w; a3 = fmaf(d, d, a3);
    d = xv2.x - cv2.x; a0 = fmaf(d, d, a0);
    d = xv2.y - cv2.y; a1 = fmaf(d, d, a1);
    d = xv2.z - cv2.z; a2 = fmaf(d, d, a2);
    d = xv2.w - cv2.w; a3 = fmaf(d, d, a3);
    d = xv3.x - cv3.x; a0 = fmaf(d, d, a0);
    d = xv3.y - cv3.y; a1 = fmaf(d, d, a1);
    d = xv3.z - cv3.z; a2 = fmaf(d, d, a2);
    d = xv3.w - cv3.w; a3 = fmaf(d, d, a3);

    float acc = (a0 + a1) + (a2 + a3);
#pragma unroll
    for (int o = 16; o > 0; o >>= 1)
        acc += __shfl_xor_sync(0xffffffffu, acc, o);

    __shared__ float sh[WARPS_PER_BLOCK];
    if (lane == 0)
        sh[wid] = fminf(fmaxf(acc, 1e-12f), 1e12f);   // clip diagonal entry
    __syncthreads();

    if (threadIdx.x == 0) {
        // fixed-order deterministic block sum (8 values)
        float bs = 0.0f;
#pragma unroll
        for (int w = 0; w < WARPS_PER_BLOCK; w++) bs += sh[w];

        // ONE atomic: accumulate Q.26 sum AND bump the block counter.
        unsigned long long q =
            (unsigned long long)__double2ll_rn((double)bs * FIX_SCALE);
        unsigned long long old =
            atomicAdd(&g_isum, q + (1ULL << CNT_SHIFT));

        if ((old >> CNT_SHIFT) == (unsigned long long)(GRID_BLOCKS - 1)) {
            // 512th arrival: grand total already in hand — no read-back.
            unsigned long long tot = (old & SUM_MASK) + q;
            double t = (double)tot * (1.0 / FIX_SCALE);
            out[0] = (float)(t / (double)BATCH + (double)(NUMC - 1) * 1e-12);
            g_isum = 0ULL;   // replay-safe reset (all contributions landed)
        }
    }
}

extern "C" void kernel_launch(void* const* d_in, const int* in_sizes, int n_in,
                              void* d_out, int out_size) {
    const float* x       = (const float*)d_in[0];
    const int*   labels  = (const int*)  d_in[1];
    const float* centers = (const float*)d_in[2];
    float*       out     = (float*)d_out;

    center_loss_kernel<<<GRID_BLOCKS, BLOCK_THREADS>>>(x, labels, centers, out);
}